// round 2
// baseline (speedup 1.0000x reference)
#include <cuda_runtime.h>
#include <cstdint>

#define NN 8192      // nodes
#define DF 128       // feature dim
#define NA 512       // anchors
#define KSEL 32      // k nearest
#define MARGINF 1.0f

// distance-kernel tiling
#define TA 32        // anchors per CTA
#define TN 64        // nodes per CTA
#define RA 4         // anchors per thread
#define RN 2         // nodes per thread
#define SROW 132     // padded smem row stride (words); conflict-free LDS.128

typedef unsigned long long u64;
#define ABSMASK2 0x7FFFFFFF7FFFFFFFULL

__device__ __forceinline__ u64 addx2(u64 a, u64 b) {
    u64 r;
    asm("add.rn.f32x2 %0, %1, %2;" : "=l"(r) : "l"(a), "l"(b));
    return r;
}

// scratch (device globals: allocation-free)
__device__ __align__(16) float g_ga[2][NA][DF];     // gathered anchor rows
__device__ float g_D[NA];                            // rowdist(a1,a2)+margin
__device__ __align__(16) float g_dist[2][NA][NN];    // full distance matrices (32 MB, L2-resident)
__device__ float g_rowLoss[2 * NA];

// ---------------------------------------------------------------------------
// Kernel 1: gather anchor rows + compute D[a] = L1(a1[a], a2[a]) + margin
// ---------------------------------------------------------------------------
__global__ void k_gather(const float* __restrict__ out1, const float* __restrict__ out2,
                         const int* __restrict__ an1, const int* __restrict__ an2) {
    int a = blockIdx.x, t = threadIdx.x;
    int i1 = an1[a], i2 = an2[a];
    float v1 = out1[(size_t)i1 * DF + t];
    float v2 = out2[(size_t)i2 * DF + t];
    g_ga[0][a][t] = v1;
    g_ga[1][a][t] = v2;
    __shared__ float red[DF];
    red[t] = fabsf(v1 - v2);
    __syncthreads();
    for (int s = DF / 2; s > 0; s >>= 1) {
        if (t < s) red[t] += red[t + s];
        __syncthreads();
    }
    if (t == 0) g_D[a] = red[0] + MARGINF;
}

// ---------------------------------------------------------------------------
// Kernel 2: L1 distance matrix via packed f32x2.
//   Node tile staged NEGATED in smem, so |a - n| = | add.f32x2(a, n_neg) |.
//   Per element-pair: 1 fma-pipe op (add) + 1 alu op (sign-clear LOP3) + 1 fma
//   (accumulate) -> fma-pipe demand halved vs scalar FADD path.
// ---------------------------------------------------------------------------
__global__ __launch_bounds__(256) void k_dist(const float* __restrict__ out1,
                                              const float* __restrict__ out2) {
    extern __shared__ float sm[];
    float* sA = sm;                 // TA rows, stride SROW
    float* sN = sm + TA * SROW;     // TN rows (negated), stride SROW

    const int side = blockIdx.z;
    const int aT = blockIdx.y;
    const int nT = blockIdx.x;
    const float* nodes = side ? out1 : out2;
    const int tid = threadIdx.x;

    // stage anchor tile
    const float4* asrc = (const float4*)&g_ga[side][aT * TA][0];
    for (int i = tid; i < TA * (DF / 4); i += 256) {
        int r = i >> 5, c = i & 31;
        *(float4*)&sA[r * SROW + c * 4] = asrc[i];
    }
    // stage node tile, negated
    const float4* nsrc = (const float4*)(nodes + (size_t)nT * TN * DF);
    for (int i = tid; i < TN * (DF / 4); i += 256) {
        int r = i >> 5, c = i & 31;
        float4 v = nsrc[i];
        v.x = -v.x; v.y = -v.y; v.z = -v.z; v.w = -v.w;
        *(float4*)&sN[r * SROW + c * 4] = v;
    }
    __syncthreads();

    const int ta = tid >> 5;   // 0..7  : anchor group (broadcast within warp)
    const int tn = tid & 31;   // 0..31 : node lane

    u64 acc[RA][RN][2];
#pragma unroll
    for (int i = 0; i < RA; i++)
#pragma unroll
        for (int j = 0; j < RN; j++) { acc[i][j][0] = 0ull; acc[i][j][1] = 0ull; }

    const float* aB = &sA[(ta * RA) * SROW];
    const float* nB = &sN[tn * SROW];

#pragma unroll 4
    for (int k = 0; k < DF; k += 4) {
        ulonglong2 av[RA], nv[RN];
#pragma unroll
        for (int i = 0; i < RA; i++) av[i] = *(const ulonglong2*)&aB[i * SROW + k];
#pragma unroll
        for (int j = 0; j < RN; j++) nv[j] = *(const ulonglong2*)&nB[j * 32 * SROW + k];
#pragma unroll
        for (int i = 0; i < RA; i++)
#pragma unroll
            for (int j = 0; j < RN; j++) {
                u64 t0 = addx2(av[i].x, nv[j].x) & ABSMASK2;   // |a - n| (packed x2)
                acc[i][j][0] = addx2(acc[i][j][0], t0);
                u64 t1 = addx2(av[i].y, nv[j].y) & ABSMASK2;
                acc[i][j][1] = addx2(acc[i][j][1], t1);
            }
    }

#pragma unroll
    for (int i = 0; i < RA; i++) {
        int A = aT * TA + ta * RA + i;
#pragma unroll
        for (int j = 0; j < RN; j++) {
            int n = nT * TN + tn + j * 32;
            u64 A0 = acc[i][j][0], A1 = acc[i][j][1];
            float s = __uint_as_float((unsigned)A0) + __uint_as_float((unsigned)(A0 >> 32)) +
                      __uint_as_float((unsigned)A1) + __uint_as_float((unsigned)(A1 >> 32));
            g_dist[side][A][n] = s;
        }
    }
}

// ---------------------------------------------------------------------------
// Kernel 3: per-row exact 32-smallest + relu-margin loss (float4-vectorized).
//   T0 = 32nd smallest of 256 per-thread chunk minima is a proven upper bound
//   on the 32nd smallest global value -> gather {v <= T0}, then 32 exact
//   extract-min passes over the tiny candidate set. Deterministic.
// ---------------------------------------------------------------------------
__global__ __launch_bounds__(256) void k_topk() {
    const int row = blockIdx.x;                 // 0..1023
    const int side = row >> 9, a = row & (NA - 1);
    const float4* __restrict__ drow4 = (const float4*)&g_dist[side][a][0];
    const int tid = threadIdx.x;

    __shared__ float smin[256];
    __shared__ float cand[2048];
    __shared__ unsigned long long wmin[8];
    __shared__ int scnt;
    __shared__ float T0s;

    float mv = 3.0e38f;
#pragma unroll
    for (int i = tid; i < NN / 4; i += 256) {
        float4 v = drow4[i];
        mv = fminf(mv, fminf(fminf(v.x, v.y), fminf(v.z, v.w)));
    }
    smin[tid] = mv;
    if (tid == 0) scnt = 0;
    __syncthreads();

    // rank of my chunk-min among the 256 (strict order via index tiebreak)
    int rank = 0;
    for (int i = 0; i < 256; i++) {
        float o = smin[i];
        rank += (o < mv) || (o == mv && i < tid);
    }
    if (rank == KSEL - 1) T0s = mv;             // exactly one thread writes
    __syncthreads();
    const float T0 = T0s;

    // gather candidates <= T0 (guaranteed to contain the 32 smallest)
    for (int i = tid; i < NN / 4; i += 256) {
        float4 v = drow4[i];
        if (v.x <= T0) { int p = atomicAdd(&scnt, 1); if (p < 2048) cand[p] = v.x; }
        if (v.y <= T0) { int p = atomicAdd(&scnt, 1); if (p < 2048) cand[p] = v.y; }
        if (v.z <= T0) { int p = atomicAdd(&scnt, 1); if (p < 2048) cand[p] = v.z; }
        if (v.w <= T0) { int p = atomicAdd(&scnt, 1); if (p < 2048) cand[p] = v.w; }
    }
    __syncthreads();
    const int cnt = min(scnt, 2048);

    const float Dv = g_D[a];
    float loss = 0.f;
    for (int it = 0; it < KSEL; it++) {
        unsigned long long key = 0xFFFFFFFFFFFFFFFFull;
        for (int i = tid; i < cnt; i += 256) {
            unsigned long long k2 =
                ((unsigned long long)__float_as_uint(cand[i]) << 32) | (unsigned)i;
            key = (k2 < key) ? k2 : key;
        }
#pragma unroll
        for (int o = 16; o; o >>= 1) {
            unsigned long long other = __shfl_xor_sync(0xffffffffu, key, o);
            key = (other < key) ? other : key;
        }
        if ((tid & 31) == 0) wmin[tid >> 5] = key;
        __syncthreads();
        if (tid == 0) {
            unsigned long long best = wmin[0];
            for (int w = 1; w < 8; w++) best = (wmin[w] < best) ? wmin[w] : best;
            float v = __uint_as_float((unsigned)(best >> 32));
            int idx = (int)(best & 0xffffffffu);
            cand[idx] = 3.0e38f;                // remove
            loss += fmaxf(Dv - v, 0.f);         // relu(D + (-d))
        }
        __syncthreads();
    }
    if (tid == 0) g_rowLoss[row] = loss;
}

// ---------------------------------------------------------------------------
// Kernel 4: deterministic final reduction + normalization
// ---------------------------------------------------------------------------
__global__ void k_final(float* __restrict__ out) {
    __shared__ float red[256];
    int t = threadIdx.x;
    float s = g_rowLoss[t] + g_rowLoss[t + 256] + g_rowLoss[t + 512] + g_rowLoss[t + 768];
    red[t] = s;
    __syncthreads();
    for (int x = 128; x > 0; x >>= 1) {
        if (t < x) red[t] += red[t + x];
        __syncthreads();
    }
    if (t == 0) out[0] = red[0] / (float)(NA * KSEL);
}

// ---------------------------------------------------------------------------
extern "C" void kernel_launch(void* const* d_in, const int* in_sizes, int n_in,
                              void* d_out, int out_size) {
    const float* out1 = (const float*)d_in[0];
    const float* out2 = (const float*)d_in[1];
    const int* an1 = (const int*)d_in[2];
    const int* an2 = (const int*)d_in[3];
    float* out = (float*)d_out;

    const int smem = (TA + TN) * SROW * (int)sizeof(float);  // 50688 B
    cudaFuncSetAttribute(k_dist, cudaFuncAttributeMaxDynamicSharedMemorySize, smem);

    k_gather<<<NA, DF>>>(out1, out2, an1, an2);
    dim3 g(NN / TN, NA / TA, 2);
    k_dist<<<g, 256, smem>>>(out1, out2);
    k_topk<<<2 * NA, 256>>>();
    k_final<<<1, 256>>>(out);
}

// round 3
// speedup vs baseline: 1.0016x; 1.0016x over previous
#include <cuda_runtime.h>
#include <cstdint>

#define NN 8192      // nodes
#define DF 128       // feature dim
#define NA 512       // anchors
#define KSEL 32      // k nearest
#define MARGINF 1.0f

// distance-kernel tiling
#define TA 32        // anchors per CTA
#define TN 64        // nodes per CTA
#define RA 4         // anchors per thread
#define RN 2         // nodes per thread
#define SROW 132     // padded smem row stride (words); conflict-free LDS.128

typedef unsigned long long u64;
#define ABSMASK2 0x7FFFFFFF7FFFFFFFULL
#define ONE2     0x3F8000003F800000ULL   // packed {1.0f, 1.0f}

// fma.rn.f32x2 -> single SASS FFMA2 (packed 2-lane fp32 FMA, fma pipe)
__device__ __forceinline__ u64 fma2(u64 a, u64 b, u64 c) {
    u64 r;
    asm("fma.rn.f32x2 %0, %1, %2, %3;" : "=l"(r) : "l"(a), "l"(b), "l"(c));
    return r;
}

// scratch (device globals: allocation-free)
__device__ __align__(16) float g_ga[2][NA][DF];     // gathered anchor rows
__device__ float g_D[NA];                            // rowdist(a1,a2)+margin
__device__ __align__(16) float g_dist[2][NA][NN];    // full distance matrices (32 MB)
__device__ float g_rowLoss[2 * NA];

// ---------------------------------------------------------------------------
// Kernel 1: gather anchor rows + compute D[a] = L1(a1[a], a2[a]) + margin
// ---------------------------------------------------------------------------
__global__ void k_gather(const float* __restrict__ out1, const float* __restrict__ out2,
                         const int* __restrict__ an1, const int* __restrict__ an2) {
    int a = blockIdx.x, t = threadIdx.x;
    int i1 = an1[a], i2 = an2[a];
    float v1 = out1[(size_t)i1 * DF + t];
    float v2 = out2[(size_t)i2 * DF + t];
    g_ga[0][a][t] = v1;
    g_ga[1][a][t] = v2;
    __shared__ float red[DF];
    red[t] = fabsf(v1 - v2);
    __syncthreads();
    for (int s = DF / 2; s > 0; s >>= 1) {
        if (t < s) red[t] += red[t + s];
        __syncthreads();
    }
    if (t == 0) g_D[a] = red[0] + MARGINF;
}

// ---------------------------------------------------------------------------
// Kernel 2: L1 distance matrix via packed FFMA2.
//   Node tile staged NEGATED in smem:
//     t   = fma.f32x2(a, 1.0x2, n_neg)   // a - n  (1 fma-pipe instr / 2 lanes)
//     t  &= 0x7FFFFFFF7FFFFFFF           // |.|    (2 LOP3, alu pipe)
//     acc = fma.f32x2(t, 1.0x2, acc)     //        (1 fma-pipe instr / 2 lanes)
//   -> 1 fma + 1 alu instr per element-pair; pipes balanced at ~2x scalar SOL.
// ---------------------------------------------------------------------------
__global__ __launch_bounds__(256) void k_dist(const float* __restrict__ out1,
                                              const float* __restrict__ out2) {
    extern __shared__ float sm[];
    float* sA = sm;                 // TA rows, stride SROW
    float* sN = sm + TA * SROW;     // TN rows (negated), stride SROW

    const int side = blockIdx.z;
    const int aT = blockIdx.y;
    const int nT = blockIdx.x;
    const float* nodes = side ? out1 : out2;
    const int tid = threadIdx.x;

    // stage anchor tile
    const float4* asrc = (const float4*)&g_ga[side][aT * TA][0];
    for (int i = tid; i < TA * (DF / 4); i += 256) {
        int r = i >> 5, c = i & 31;
        *(float4*)&sA[r * SROW + c * 4] = asrc[i];
    }
    // stage node tile, negated
    const float4* nsrc = (const float4*)(nodes + (size_t)nT * TN * DF);
    for (int i = tid; i < TN * (DF / 4); i += 256) {
        int r = i >> 5, c = i & 31;
        float4 v = nsrc[i];
        v.x = -v.x; v.y = -v.y; v.z = -v.z; v.w = -v.w;
        *(float4*)&sN[r * SROW + c * 4] = v;
    }
    __syncthreads();

    const int ta = tid >> 5;   // 0..7  : anchor group (broadcast within warp)
    const int tn = tid & 31;   // 0..31 : node lane

    u64 acc[RA][RN][2];
#pragma unroll
    for (int i = 0; i < RA; i++)
#pragma unroll
        for (int j = 0; j < RN; j++) { acc[i][j][0] = 0ull; acc[i][j][1] = 0ull; }

    const float* aB = &sA[(ta * RA) * SROW];
    const float* nB = &sN[tn * SROW];
    const u64 one2 = ONE2;

#pragma unroll 4
    for (int k = 0; k < DF; k += 4) {
        ulonglong2 av[RA], nv[RN];
#pragma unroll
        for (int i = 0; i < RA; i++) av[i] = *(const ulonglong2*)&aB[i * SROW + k];
#pragma unroll
        for (int j = 0; j < RN; j++) nv[j] = *(const ulonglong2*)&nB[j * 32 * SROW + k];
#pragma unroll
        for (int i = 0; i < RA; i++)
#pragma unroll
            for (int j = 0; j < RN; j++) {
                u64 t0 = fma2(av[i].x, one2, nv[j].x) & ABSMASK2;  // |a - n| x2
                acc[i][j][0] = fma2(t0, one2, acc[i][j][0]);
                u64 t1 = fma2(av[i].y, one2, nv[j].y) & ABSMASK2;
                acc[i][j][1] = fma2(t1, one2, acc[i][j][1]);
            }
    }

#pragma unroll
    for (int i = 0; i < RA; i++) {
        int A = aT * TA + ta * RA + i;
#pragma unroll
        for (int j = 0; j < RN; j++) {
            int n = nT * TN + tn + j * 32;
            u64 A0 = acc[i][j][0], A1 = acc[i][j][1];
            float s = __uint_as_float((unsigned)A0) + __uint_as_float((unsigned)(A0 >> 32)) +
                      __uint_as_float((unsigned)A1) + __uint_as_float((unsigned)(A1 >> 32));
            g_dist[side][A][n] = s;
        }
    }
}

// ---------------------------------------------------------------------------
// Kernel 3: per-row exact 32-smallest + relu-margin loss (float4-vectorized).
//   T0 = 32nd smallest of 256 per-thread chunk minima is a proven upper bound
//   on the 32nd smallest global value -> gather {v <= T0}, then 32 exact
//   extract-min passes over the tiny candidate set. Deterministic.
// ---------------------------------------------------------------------------
__global__ __launch_bounds__(256) void k_topk() {
    const int row = blockIdx.x;                 // 0..1023
    const int side = row >> 9, a = row & (NA - 1);
    const float4* __restrict__ drow4 = (const float4*)&g_dist[side][a][0];
    const int tid = threadIdx.x;

    __shared__ float smin[256];
    __shared__ float cand[2048];
    __shared__ unsigned long long wmin[8];
    __shared__ int scnt;
    __shared__ float T0s;

    float mv = 3.0e38f;
#pragma unroll
    for (int i = tid; i < NN / 4; i += 256) {
        float4 v = drow4[i];
        mv = fminf(mv, fminf(fminf(v.x, v.y), fminf(v.z, v.w)));
    }
    smin[tid] = mv;
    if (tid == 0) scnt = 0;
    __syncthreads();

    // rank of my chunk-min among the 256 (strict order via index tiebreak)
    int rank = 0;
    for (int i = 0; i < 256; i++) {
        float o = smin[i];
        rank += (o < mv) || (o == mv && i < tid);
    }
    if (rank == KSEL - 1) T0s = mv;             // exactly one thread writes
    __syncthreads();
    const float T0 = T0s;

    // gather candidates <= T0 (guaranteed to contain the 32 smallest)
    for (int i = tid; i < NN / 4; i += 256) {
        float4 v = drow4[i];
        if (v.x <= T0) { int p = atomicAdd(&scnt, 1); if (p < 2048) cand[p] = v.x; }
        if (v.y <= T0) { int p = atomicAdd(&scnt, 1); if (p < 2048) cand[p] = v.y; }
        if (v.z <= T0) { int p = atomicAdd(&scnt, 1); if (p < 2048) cand[p] = v.z; }
        if (v.w <= T0) { int p = atomicAdd(&scnt, 1); if (p < 2048) cand[p] = v.w; }
    }
    __syncthreads();
    const int cnt = min(scnt, 2048);

    const float Dv = g_D[a];
    float loss = 0.f;
    for (int it = 0; it < KSEL; it++) {
        unsigned long long key = 0xFFFFFFFFFFFFFFFFull;
        for (int i = tid; i < cnt; i += 256) {
            unsigned long long k2 =
                ((unsigned long long)__float_as_uint(cand[i]) << 32) | (unsigned)i;
            key = (k2 < key) ? k2 : key;
        }
#pragma unroll
        for (int o = 16; o; o >>= 1) {
            unsigned long long other = __shfl_xor_sync(0xffffffffu, key, o);
            key = (other < key) ? other : key;
        }
        if ((tid & 31) == 0) wmin[tid >> 5] = key;
        __syncthreads();
        if (tid == 0) {
            unsigned long long best = wmin[0];
            for (int w = 1; w < 8; w++) best = (wmin[w] < best) ? wmin[w] : best;
            float v = __uint_as_float((unsigned)(best >> 32));
            int idx = (int)(best & 0xffffffffu);
            cand[idx] = 3.0e38f;                // remove
            loss += fmaxf(Dv - v, 0.f);         // relu(D + (-d))
        }
        __syncthreads();
    }
    if (tid == 0) g_rowLoss[row] = loss;
}

// ---------------------------------------------------------------------------
// Kernel 4: deterministic final reduction + normalization
// ---------------------------------------------------------------------------
__global__ void k_final(float* __restrict__ out) {
    __shared__ float red[256];
    int t = threadIdx.x;
    float s = g_rowLoss[t] + g_rowLoss[t + 256] + g_rowLoss[t + 512] + g_rowLoss[t + 768];
    red[t] = s;
    __syncthreads();
    for (int x = 128; x > 0; x >>= 1) {
        if (t < x) red[t] += red[t + x];
        __syncthreads();
    }
    if (t == 0) out[0] = red[0] / (float)(NA * KSEL);
}

// ---------------------------------------------------------------------------
extern "C" void kernel_launch(void* const* d_in, const int* in_sizes, int n_in,
                              void* d_out, int out_size) {
    const float* out1 = (const float*)d_in[0];
    const float* out2 = (const float*)d_in[1];
    const int* an1 = (const int*)d_in[2];
    const int* an2 = (const int*)d_in[3];
    float* out = (float*)d_out;

    const int smem = (TA + TN) * SROW * (int)sizeof(float);  // 50688 B
    cudaFuncSetAttribute(k_dist, cudaFuncAttributeMaxDynamicSharedMemorySize, smem);

    k_gather<<<NA, DF>>>(out1, out2, an1, an2);
    dim3 g(NN / TN, NA / TA, 2);
    k_dist<<<g, 256, smem>>>(out1, out2);
    k_topk<<<2 * NA, 256>>>();
    k_final<<<1, 256>>>(out);
}

// round 4
// speedup vs baseline: 1.1072x; 1.1055x over previous
#include <cuda_runtime.h>
#include <cstdint>

#define NN 8192      // nodes
#define DF 128       // feature dim
#define NA 512       // anchors
#define KSEL 32      // k nearest
#define MARGINF 1.0f

// distance-kernel tiling
#define TA 32        // anchors per CTA
#define TN 64        // nodes per CTA
#define RA 4         // anchors per thread
#define RN 2         // nodes per thread
#define SROW 132     // padded smem row stride (words); conflict-free LDS.128

// scratch (device globals: allocation-free)
__device__ float g_D[NA];                            // unused placeholder (kept for layout)
__device__ __align__(16) float g_dist[2][NA][NN];    // full distance matrices (32 MB)
__device__ float g_rowLoss[2 * NA];
__device__ unsigned int g_done;

// ---------------------------------------------------------------------------
// Kernel A: L1 distance matrix, GEMM-style smem tiling, anchor gather inlined.
//   side 0: out1[anchor1] vs out2 ;  side 1: out2[anchor2] vs out1
//   Scalar fp32 math: 2 FADD/element, dual-routed across fma+alu pipes
//   (measured issue-saturated ~4.2 instr/cyc/SM).
// ---------------------------------------------------------------------------
__global__ __launch_bounds__(256) void k_dist(const float* __restrict__ out1,
                                              const float* __restrict__ out2,
                                              const int* __restrict__ an1,
                                              const int* __restrict__ an2) {
    extern __shared__ float sm[];
    float* sA = sm;                 // TA rows, stride SROW
    float* sN = sm + TA * SROW;     // TN rows, stride SROW

    const int side = blockIdx.z;
    const int aT = blockIdx.y;
    const int nT = blockIdx.x;
    const float* __restrict__ abase = side ? out2 : out1;
    const int* __restrict__ aidx = side ? an2 : an1;
    const float* __restrict__ nodes = side ? out1 : out2;
    const int tid = threadIdx.x;

    // reset completion counter for kernel B (once per launch)
    if (blockIdx.x == 0 && blockIdx.y == 0 && blockIdx.z == 0 && tid == 0) g_done = 0u;

    // stage anchor tile: gather 32 anchor rows directly from the node matrix
    for (int i = tid; i < TA * (DF / 4); i += 256) {
        int r = i >> 5, c = i & 31;
        int node = aidx[aT * TA + r];
        *(float4*)&sA[r * SROW + c * 4] =
            *(const float4*)&abase[(size_t)node * DF + c * 4];
    }
    // stage node tile (contiguous block of node matrix)
    const float4* nsrc = (const float4*)(nodes + (size_t)nT * TN * DF);
    for (int i = tid; i < TN * (DF / 4); i += 256) {
        int r = i >> 5, c = i & 31;
        *(float4*)&sN[r * SROW + c * 4] = nsrc[i];
    }
    __syncthreads();

    const int ta = tid >> 5;   // 0..7  : anchor group (broadcast within warp)
    const int tn = tid & 31;   // 0..31 : node lane
    float acc[RA][RN];
#pragma unroll
    for (int i = 0; i < RA; i++)
#pragma unroll
        for (int j = 0; j < RN; j++) acc[i][j] = 0.f;

    const float* aB = &sA[(ta * RA) * SROW];
    const float* nB = &sN[tn * SROW];

#pragma unroll 2
    for (int k = 0; k < DF; k += 4) {
        float4 av[RA], nv[RN];
#pragma unroll
        for (int i = 0; i < RA; i++) av[i] = *(const float4*)&aB[i * SROW + k];
#pragma unroll
        for (int j = 0; j < RN; j++) nv[j] = *(const float4*)&nB[j * 32 * SROW + k];
#pragma unroll
        for (int i = 0; i < RA; i++)
#pragma unroll
            for (int j = 0; j < RN; j++) {
                float s = acc[i][j];
                s += fabsf(av[i].x - nv[j].x);
                s += fabsf(av[i].y - nv[j].y);
                s += fabsf(av[i].z - nv[j].z);
                s += fabsf(av[i].w - nv[j].w);
                acc[i][j] = s;
            }
    }

#pragma unroll
    for (int i = 0; i < RA; i++) {
        int A = aT * TA + ta * RA + i;
#pragma unroll
        for (int j = 0; j < RN; j++) {
            int n = nT * TN + tn + j * 32;
            g_dist[side][A][n] = acc[i][j];
        }
    }
}

// ---------------------------------------------------------------------------
// Kernel B: per-row exact 32-smallest + relu-margin loss; D computed in-block;
//   last block (threadfence ticket) does the deterministic final reduction.
//   T0 = 32nd smallest of 256 per-thread chunk minima is a proven upper bound
//   on the 32nd smallest global value -> gather {v <= T0}, then 32 exact
//   extract-min passes over the tiny candidate set.
// ---------------------------------------------------------------------------
__global__ __launch_bounds__(256) void k_topk(const float* __restrict__ out1,
                                              const float* __restrict__ out2,
                                              const int* __restrict__ an1,
                                              const int* __restrict__ an2,
                                              float* __restrict__ outp) {
    const int row = blockIdx.x;                 // 0..1023
    const int side = row >> 9, a = row & (NA - 1);
    const float4* __restrict__ drow4 = (const float4*)&g_dist[side][a][0];
    const int tid = threadIdx.x;

    __shared__ float smin[256];
    __shared__ float cand[2048];
    __shared__ unsigned long long wmin[8];
    __shared__ int scnt;
    __shared__ float T0s;
    __shared__ float Dsh;
    __shared__ unsigned int ticket;

    // ---- D[a] = L1(out1[an1[a]], out2[an2[a]]) + margin (threads 0..127) ----
    {
        float part = 0.f;
        if (tid < DF) {
            int i1 = an1[a], i2 = an2[a];
            part = fabsf(out1[(size_t)i1 * DF + tid] - out2[(size_t)i2 * DF + tid]);
        }
        // warp-level reduce then cross-warp via smin (reused before min-scan)
        for (int o = 16; o; o >>= 1) part += __shfl_xor_sync(0xffffffffu, part, o);
        if ((tid & 31) == 0) smin[tid >> 5] = part;
        __syncthreads();
        if (tid == 0) Dsh = smin[0] + smin[1] + smin[2] + smin[3] + MARGINF;
        __syncthreads();
    }

    // ---- per-thread chunk minima ----
    float mv = 3.0e38f;
#pragma unroll
    for (int i = tid; i < NN / 4; i += 256) {
        float4 v = drow4[i];
        mv = fminf(mv, fminf(fminf(v.x, v.y), fminf(v.z, v.w)));
    }
    smin[tid] = mv;
    if (tid == 0) scnt = 0;
    __syncthreads();

    // rank of my chunk-min among the 256 (strict order via index tiebreak)
    int rank = 0;
    for (int i = 0; i < 256; i++) {
        float o = smin[i];
        rank += (o < mv) || (o == mv && i < tid);
    }
    if (rank == KSEL - 1) T0s = mv;             // exactly one thread writes
    __syncthreads();
    const float T0 = T0s;

    // gather candidates <= T0 (guaranteed to contain the 32 smallest)
    for (int i = tid; i < NN / 4; i += 256) {
        float4 v = drow4[i];
        if (v.x <= T0) { int p = atomicAdd(&scnt, 1); if (p < 2048) cand[p] = v.x; }
        if (v.y <= T0) { int p = atomicAdd(&scnt, 1); if (p < 2048) cand[p] = v.y; }
        if (v.z <= T0) { int p = atomicAdd(&scnt, 1); if (p < 2048) cand[p] = v.z; }
        if (v.w <= T0) { int p = atomicAdd(&scnt, 1); if (p < 2048) cand[p] = v.w; }
    }
    __syncthreads();
    const int cnt = min(scnt, 2048);

    const float Dv = Dsh;
    float loss = 0.f;
    for (int it = 0; it < KSEL; it++) {
        unsigned long long key = 0xFFFFFFFFFFFFFFFFull;
        for (int i = tid; i < cnt; i += 256) {
            unsigned long long k2 =
                ((unsigned long long)__float_as_uint(cand[i]) << 32) | (unsigned)i;
            key = (k2 < key) ? k2 : key;
        }
#pragma unroll
        for (int o = 16; o; o >>= 1) {
            unsigned long long other = __shfl_xor_sync(0xffffffffu, key, o);
            key = (other < key) ? other : key;
        }
        if ((tid & 31) == 0) wmin[tid >> 5] = key;
        __syncthreads();
        if (tid == 0) {
            unsigned long long best = wmin[0];
            for (int w = 1; w < 8; w++) best = (wmin[w] < best) ? wmin[w] : best;
            float v = __uint_as_float((unsigned)(best >> 32));
            int idx = (int)(best & 0xffffffffu);
            cand[idx] = 3.0e38f;                // remove
            loss += fmaxf(Dv - v, 0.f);         // relu(D + (-d))
        }
        __syncthreads();
    }
    if (tid == 0) {
        g_rowLoss[row] = loss;
        __threadfence();
        ticket = atomicAdd(&g_done, 1u);
    }
    __syncthreads();

    // ---- last block: deterministic final reduction ----
    if (ticket == 2 * NA - 1) {
        float s = g_rowLoss[tid] + g_rowLoss[tid + 256] +
                  g_rowLoss[tid + 512] + g_rowLoss[tid + 768];
        smin[tid] = s;
        __syncthreads();
        for (int x = 128; x > 0; x >>= 1) {
            if (tid < x) smin[tid] += smin[tid + x];
            __syncthreads();
        }
        if (tid == 0) outp[0] = smin[0] / (float)(NA * KSEL);
    }
}

// ---------------------------------------------------------------------------
extern "C" void kernel_launch(void* const* d_in, const int* in_sizes, int n_in,
                              void* d_out, int out_size) {
    const float* out1 = (const float*)d_in[0];
    const float* out2 = (const float*)d_in[1];
    const int* an1 = (const int*)d_in[2];
    const int* an2 = (const int*)d_in[3];
    float* out = (float*)d_out;

    const int smem = (TA + TN) * SROW * (int)sizeof(float);  // 50688 B
    cudaFuncSetAttribute(k_dist, cudaFuncAttributeMaxDynamicSharedMemorySize, smem);

    dim3 g(NN / TN, NA / TA, 2);
    k_dist<<<g, 256, smem>>>(out1, out2, an1, an2);
    k_topk<<<2 * NA, 256>>>(out1, out2, an1, an2, out);
}

// round 5
// speedup vs baseline: 1.3816x; 1.2478x over previous
#include <cuda_runtime.h>
#include <cstdint>

#define NN 8192      // nodes
#define DF 128       // feature dim
#define NA 512       // anchors
#define KSEL 32      // k nearest
#define MARGINF 1.0f

// distance-kernel tiling
#define TA 32
#define TN 64
#define RA 4
#define RN 2
#define SROW 132     // padded smem row stride (words); conflict-free LDS.128

#define MAXCAND 2048

// scratch (device globals: allocation-free)
__device__ __align__(16) float g_dist[2][NA][NN];    // full distance matrices (32 MB)
__device__ float g_rowLoss[2 * NA];
__device__ unsigned int g_done;

// ---------------------------------------------------------------------------
// Kernel A: L1 distance matrix, GEMM-style smem tiling, anchor gather inlined.
// ---------------------------------------------------------------------------
__global__ __launch_bounds__(256) void k_dist(const float* __restrict__ out1,
                                              const float* __restrict__ out2,
                                              const int* __restrict__ an1,
                                              const int* __restrict__ an2) {
    extern __shared__ float sm[];
    float* sA = sm;                 // TA rows, stride SROW
    float* sN = sm + TA * SROW;     // TN rows, stride SROW

    const int side = blockIdx.z;
    const int aT = blockIdx.y;
    const int nT = blockIdx.x;
    const float* __restrict__ abase = side ? out2 : out1;
    const int* __restrict__ aidx = side ? an2 : an1;
    const float* __restrict__ nodes = side ? out1 : out2;
    const int tid = threadIdx.x;

    if (blockIdx.x == 0 && blockIdx.y == 0 && blockIdx.z == 0 && tid == 0) g_done = 0u;

    // stage anchor tile: gather 32 anchor rows
    for (int i = tid; i < TA * (DF / 4); i += 256) {
        int r = i >> 5, c = i & 31;
        int node = aidx[aT * TA + r];
        *(float4*)&sA[r * SROW + c * 4] =
            *(const float4*)&abase[(size_t)node * DF + c * 4];
    }
    // stage node tile
    const float4* nsrc = (const float4*)(nodes + (size_t)nT * TN * DF);
    for (int i = tid; i < TN * (DF / 4); i += 256) {
        int r = i >> 5, c = i & 31;
        *(float4*)&sN[r * SROW + c * 4] = nsrc[i];
    }
    __syncthreads();

    const int ta = tid >> 5;
    const int tn = tid & 31;
    float acc[RA][RN];
#pragma unroll
    for (int i = 0; i < RA; i++)
#pragma unroll
        for (int j = 0; j < RN; j++) acc[i][j] = 0.f;

    const float* aB = &sA[(ta * RA) * SROW];
    const float* nB = &sN[tn * SROW];

#pragma unroll 2
    for (int k = 0; k < DF; k += 4) {
        float4 av[RA], nv[RN];
#pragma unroll
        for (int i = 0; i < RA; i++) av[i] = *(const float4*)&aB[i * SROW + k];
#pragma unroll
        for (int j = 0; j < RN; j++) nv[j] = *(const float4*)&nB[j * 32 * SROW + k];
#pragma unroll
        for (int i = 0; i < RA; i++)
#pragma unroll
            for (int j = 0; j < RN; j++) {
                float s = acc[i][j];
                s += fabsf(av[i].x - nv[j].x);
                s += fabsf(av[i].y - nv[j].y);
                s += fabsf(av[i].z - nv[j].z);
                s += fabsf(av[i].w - nv[j].w);
                acc[i][j] = s;
            }
    }

#pragma unroll
    for (int i = 0; i < RA; i++) {
        int A = aT * TA + ta * RA + i;
#pragma unroll
        for (int j = 0; j < RN; j++) {
            int n = nT * TN + tn + j * 32;
            g_dist[side][A][n] = acc[i][j];
        }
    }
}

// ---------------------------------------------------------------------------
// Kernel B: per-row exact 32-smallest + relu-margin loss.
//   T0 bound = max over 32 disjoint-group minima (valid upper bound on the
//   32nd smallest). Gather {v <= T0}. Radix-select (4x 8-bit passes) finds
//   the exact 32nd smallest T and L = #{v < T}; then
//   loss = sum_{v<T} relu(D-v) + (32-L)*relu(D-T).   Deterministic.
//   Last block (ticket) does the final reduction.
// ---------------------------------------------------------------------------
__global__ __launch_bounds__(256) void k_topk(const float* __restrict__ out1,
                                              const float* __restrict__ out2,
                                              const int* __restrict__ an1,
                                              const int* __restrict__ an2,
                                              float* __restrict__ outp) {
    const int row = blockIdx.x;                 // 0..1023
    const int side = row >> 9, a = row & (NA - 1);
    const float4* __restrict__ drow4 = (const float4*)&g_dist[side][a][0];
    const int tid = threadIdx.x;
    const int lane = tid & 31, wid = tid >> 5;

    __shared__ float sred[256];                 // scratch (minima / reductions)
    __shared__ float cand[MAXCAND];
    __shared__ unsigned hist[256];
    __shared__ unsigned wsum[8];
    __shared__ float wpart[8];
    __shared__ int scnt;
    __shared__ float T0s;
    __shared__ float Dsh;
    __shared__ unsigned selByte, selExc;
    __shared__ unsigned int ticket;

    // ---- D[a] = L1(out1[an1[a]], out2[an2[a]]) + margin ----
    {
        float part = 0.f;
        if (tid < DF) {
            int i1 = an1[a], i2 = an2[a];
            part = fabsf(out1[(size_t)i1 * DF + tid] - out2[(size_t)i2 * DF + tid]);
        }
        for (int o = 16; o; o >>= 1) part += __shfl_xor_sync(0xffffffffu, part, o);
        if (lane == 0) sred[wid] = part;
        __syncthreads();
        if (tid == 0) Dsh = sred[0] + sred[1] + sred[2] + sred[3] + MARGINF;
    }
    if (tid == 0) scnt = 0;

    // ---- per-thread minima over strided float4 chunks ----
    float mv = 3.0e38f;
#pragma unroll
    for (int i = tid; i < NN / 4; i += 256) {
        float4 v = drow4[i];
        mv = fminf(mv, fminf(fminf(v.x, v.y), fminf(v.z, v.w)));
    }
    __syncthreads();               // protects sred reuse (D-phase done)
    sred[tid] = mv;
    __syncthreads();

    // T0 = max over 32 group minima (group = lane across the 8 warps)
    if (tid < 32) {
        float gm = sred[tid];
#pragma unroll
        for (int w = 1; w < 8; w++) gm = fminf(gm, sred[w * 32 + tid]);
        float t0 = gm;
#pragma unroll
        for (int o = 16; o; o >>= 1) t0 = fmaxf(t0, __shfl_xor_sync(0xffffffffu, t0, o));
        if (tid == 0) T0s = t0;
    }
    __syncthreads();
    const float T0 = T0s;

    // ---- gather candidates <= T0 ----
    for (int i = tid; i < NN / 4; i += 256) {
        float4 v = drow4[i];
        if (v.x <= T0) { int p = atomicAdd(&scnt, 1); if (p < MAXCAND) cand[p] = v.x; }
        if (v.y <= T0) { int p = atomicAdd(&scnt, 1); if (p < MAXCAND) cand[p] = v.y; }
        if (v.z <= T0) { int p = atomicAdd(&scnt, 1); if (p < MAXCAND) cand[p] = v.z; }
        if (v.w <= T0) { int p = atomicAdd(&scnt, 1); if (p < MAXCAND) cand[p] = v.w; }
    }
    __syncthreads();
    const int cnt = min(scnt, MAXCAND);

    // ---- radix select: exact 32nd smallest (positive floats: uint order) ----
    unsigned prefix = 0;     // high bits of answer discovered so far
    unsigned target = KSEL;  // 1-based rank within matched-prefix subset
    unsigned below = 0;      // #elements strictly below answer
#pragma unroll
    for (int p = 3; p >= 0; --p) {
        const int shift = p * 8;
        hist[tid] = 0;
        __syncthreads();
        for (int i = tid; i < cnt; i += 256) {
            unsigned u = __float_as_uint(cand[i]);
            bool match = (p == 3) || ((u >> (shift + 8)) == (prefix >> (shift + 8)));
            if (match) atomicAdd(&hist[(u >> shift) & 0xFFu], 1u);
        }
        __syncthreads();
        // block inclusive scan over 256 bins
        unsigned h = hist[tid];
        unsigned inc = h;
#pragma unroll
        for (int o = 1; o < 32; o <<= 1) {
            unsigned n = __shfl_up_sync(0xffffffffu, inc, o);
            if (lane >= o) inc += n;
        }
        if (lane == 31) wsum[wid] = inc;
        __syncthreads();
        unsigned woff = 0;
        for (int w = 0; w < wid; w++) woff += wsum[w];
        inc += woff;
        unsigned exc = inc - h;
        if (exc < target && target <= inc) { selByte = (unsigned)tid; selExc = exc; }
        __syncthreads();
        prefix |= (selByte << shift);
        target -= selExc;
        below += selExc;
        __syncthreads();
    }
    const float Tval = __uint_as_float(prefix);
    const float Dv = Dsh;

    // ---- final: loss = sum_{v<T} relu(D-v) + (32-below)*relu(D-T) ----
    float part = 0.f;
    for (int i = tid; i < cnt; i += 256) {
        float v = cand[i];
        if (v < Tval) part += fmaxf(Dv - v, 0.f);
    }
#pragma unroll
    for (int o = 16; o; o >>= 1) part += __shfl_xor_sync(0xffffffffu, part, o);
    if (lane == 0) wpart[wid] = part;
    __syncthreads();
    if (tid == 0) {
        float loss = 0.f;
#pragma unroll
        for (int w = 0; w < 8; w++) loss += wpart[w];
        loss += (float)(KSEL - (int)below) * fmaxf(Dv - Tval, 0.f);
        g_rowLoss[row] = loss;
        __threadfence();
        ticket = atomicAdd(&g_done, 1u);
    }
    __syncthreads();

    // ---- last block: deterministic final reduction ----
    if (ticket == 2 * NA - 1) {
        float s = g_rowLoss[tid] + g_rowLoss[tid + 256] +
                  g_rowLoss[tid + 512] + g_rowLoss[tid + 768];
        sred[tid] = s;
        __syncthreads();
        for (int x = 128; x > 0; x >>= 1) {
            if (tid < x) sred[tid] += sred[tid + x];
            __syncthreads();
        }
        if (tid == 0) outp[0] = sred[0] / (float)(NA * KSEL);
    }
}

// ---------------------------------------------------------------------------
extern "C" void kernel_launch(void* const* d_in, const int* in_sizes, int n_in,
                              void* d_out, int out_size) {
    const float* out1 = (const float*)d_in[0];
    const float* out2 = (const float*)d_in[1];
    const int* an1 = (const int*)d_in[2];
    const int* an2 = (const int*)d_in[3];
    float* out = (float*)d_out;

    const int smem = (TA + TN) * SROW * (int)sizeof(float);  // 50688 B
    cudaFuncSetAttribute(k_dist, cudaFuncAttributeMaxDynamicSharedMemorySize, smem);

    dim3 g(NN / TN, NA / TA, 2);
    k_dist<<<g, 256, smem>>>(out1, out2, an1, an2);
    k_topk<<<2 * NA, 256>>>(out1, out2, an1, an2, out);
}